// round 4
// baseline (speedup 1.0000x reference)
#include <cuda_runtime.h>
#include <cuda_fp16.h>
#include <math.h>

#define DD 64
#define NMAX 50000
#define EMAX 800000
#define INV_SQRT2 0.70710678118654752440f

// ---- scratch (device globals: allocation-free) ----
__device__ __half g_embh[(size_t)EMAX * DD]; // bond output, fp16, dst-sorted order (102MB, ~L2-resident)
__device__ float g_h[(size_t)NMAX * DD];     // MLP output (pre-BN)
__device__ float g_xa[(size_t)NMAX * DD];    // x ping
__device__ float g_xb[(size_t)NMAX * DD];    // x pong
__device__ float g_bsum[DD];                 // BN sum per feature
__device__ float g_bsq[DD];                  // BN sumsq per feature
// sort scratch
__device__ int g_off[NMAX + 1];              // CSR offsets by dst
__device__ int g_cur[NMAX];                  // counts / cursors
__device__ int g_srcs[EMAX];                 // src id, permuted into dst order
__device__ int g_pos[EMAX];                  // sorted position of original edge e

__device__ __forceinline__ float gelu_exact(float v) {
    // jax.nn.gelu(approximate=False) = 0.5 v (1 + erf(v/sqrt(2)))
    return 0.5f * v * (1.0f + erff(v * 0.70710678118654752440f));
}

__device__ __forceinline__ const float* sel_in(int s, const float* ext) {
    return (s == 0) ? ext : ((s == 1) ? g_xa : g_xb);
}
__device__ __forceinline__ float* sel_out(int s, float* ext) {
    return (s == 0) ? ext : ((s == 1) ? g_xa : g_xb);
}

// ============================================================
// Sort phase: counting sort of edges by dst
// ============================================================
__global__ void k_cnt0(int N)
{
    int i = blockIdx.x * blockDim.x + threadIdx.x;
    if (i < N) g_cur[i] = 0;
}

__global__ void k_count(const int* __restrict__ dst, int E)
{
    int e = blockIdx.x * blockDim.x + threadIdx.x;
    if (e < E) atomicAdd(&g_cur[dst[e]], 1);
}

__global__ void __launch_bounds__(1024) k_scan(int N, int E)
{
    __shared__ int ssum[1024];
    int t = threadIdx.x;
    int C = (N + 1023) >> 10;
    int beg = t * C;
    int end = min(beg + C, N);
    int s = 0;
    for (int i = beg; i < end; i++) s += g_cur[i];
    ssum[t] = s;
    __syncthreads();
    for (int off = 1; off < 1024; off <<= 1) {
        int v = (t >= off) ? ssum[t - off] : 0;
        __syncthreads();
        ssum[t] += v;
        __syncthreads();
    }
    int run = (t == 0) ? 0 : ssum[t - 1];
    for (int i = beg; i < end; i++) {
        int c = g_cur[i];
        g_off[i] = run;
        run += c;
        g_cur[i] = 0;
    }
    if (beg < N && end == N) g_off[N] = run;
}

__global__ void k_scatter(const int* __restrict__ src,
                          const int* __restrict__ dst, int E)
{
    int e = blockIdx.x * blockDim.x + threadIdx.x;
    if (e >= E) return;
    int t = dst[e];
    int r = atomicAdd(&g_cur[t], 1);
    int p = g_off[t] + r;
    g_pos[e]  = p;
    g_srcs[p] = src[e];
}

// ============================================================
// K_bond: emb = attr @ W_be + b_be  -> fp16, dst-sorted order.
// 64 threads/block (thread owns output dim d); 4 rows/iter = 4
// independent FMA chains. attr row loads are warp-uniform float4
// (L1 broadcast).
// ============================================================
__global__ void __launch_bounds__(64) k_bond(
    const float* __restrict__ attr,
    const float* __restrict__ Wbe,
    const float* __restrict__ bbe, int E)
{
    int d = threadIdx.x;

    float w[DD];
#pragma unroll
    for (int k = 0; k < DD; k++) w[k] = Wbe[k * DD + d];
    float bias = bbe[d];

    for (int base = blockIdx.x * 4; base < E; base += gridDim.x * 4) {
        int r1 = min(base + 1, E - 1);
        int r2 = min(base + 2, E - 1);
        int r3 = min(base + 3, E - 1);
        const float4* a0 = (const float4*)(attr + (size_t)base * DD);
        const float4* a1 = (const float4*)(attr + (size_t)r1 * DD);
        const float4* a2 = (const float4*)(attr + (size_t)r2 * DD);
        const float4* a3 = (const float4*)(attr + (size_t)r3 * DD);
        float acc0 = bias, acc1 = bias, acc2 = bias, acc3 = bias;
#pragma unroll
        for (int k4 = 0; k4 < 16; k4++) {
            float4 v0 = a0[k4], v1 = a1[k4], v2 = a2[k4], v3 = a3[k4];
            acc0 = fmaf(v0.x, w[4*k4+0], acc0); acc0 = fmaf(v0.y, w[4*k4+1], acc0);
            acc0 = fmaf(v0.z, w[4*k4+2], acc0); acc0 = fmaf(v0.w, w[4*k4+3], acc0);
            acc1 = fmaf(v1.x, w[4*k4+0], acc1); acc1 = fmaf(v1.y, w[4*k4+1], acc1);
            acc1 = fmaf(v1.z, w[4*k4+2], acc1); acc1 = fmaf(v1.w, w[4*k4+3], acc1);
            acc2 = fmaf(v2.x, w[4*k4+0], acc2); acc2 = fmaf(v2.y, w[4*k4+1], acc2);
            acc2 = fmaf(v2.z, w[4*k4+2], acc2); acc2 = fmaf(v2.w, w[4*k4+3], acc2);
            acc3 = fmaf(v3.x, w[4*k4+0], acc3); acc3 = fmaf(v3.y, w[4*k4+1], acc3);
            acc3 = fmaf(v3.z, w[4*k4+2], acc3); acc3 = fmaf(v3.w, w[4*k4+3], acc3);
        }
        g_embh[(size_t)g_pos[base] * DD + d] = __float2half_rn(acc0);
        if (base + 1 < E) g_embh[(size_t)g_pos[base+1] * DD + d] = __float2half_rn(acc1);
        if (base + 2 < E) g_embh[(size_t)g_pos[base+2] * DD + d] = __float2half_rn(acc2);
        if (base + 3 < E) g_embh[(size_t)g_pos[base+3] * DD + d] = __float2half_rn(acc3);
    }
}

// ============================================================
// K_zstat: zero BN accumulators (tiny, once per layer)
// ============================================================
__global__ void k_zstat()
{
    if (threadIdx.x < DD) { g_bsum[threadIdx.x] = 0.f; g_bsq[threadIdx.x] = 0.f; }
}

// ============================================================
// K_mlp (fused agg + MLP):
//   agg_n = (1+eps) x[n] + sum_{e->n} gelu(x[src_e] + emb_e)
//   h_n   = gelu(agg_n @ W1 + b1) @ W2 + b2 ; accumulate BN stats
// 64 threads/block (thread owns dim d), 4 nodes per iteration.
// ============================================================
__global__ void __launch_bounds__(64) k_mlp(
    int xsel, const float* __restrict__ xext,
    const float* __restrict__ W1, const float* __restrict__ b1,
    const float* __restrict__ W2, const float* __restrict__ b2,
    const float* __restrict__ epsp, int layer, int N)
{
    __shared__ float4 s_in4[4][16];
    __shared__ float4 s_h14[4][16];
    float* s_in = (float*)s_in4;
    float* s_h1 = (float*)s_h14;

    const float* x = sel_in(xsel, xext);
    int d = threadIdx.x;

    float w1[DD], w2[DD];
#pragma unroll
    for (int k = 0; k < DD; k++) w1[k] = W1[k * DD + d];
#pragma unroll
    for (int k = 0; k < DD; k++) w2[k] = W2[k * DD + d];
    float bb1 = b1[d], bb2 = b2[d];
    float eps1 = 1.0f + epsp[layer];

    float lsum = 0.f, lsq = 0.f;

    for (int base = blockIdx.x * 4; base < N; base += gridDim.x * 4) {
        int nr = min(4, N - base);

        // ---- fused aggregation: thread d accumulates dim d of each node ----
#pragma unroll
        for (int r = 0; r < 4; r++) {
            if (r < nr) {
                int n = base + r;
                int beg = g_off[n], end = g_off[n + 1];
                float agg = 0.f;
                for (int e = beg; e < end; e++) {
                    int s = __ldg(&g_srcs[e]);
                    float v = __half2float(g_embh[(size_t)e * DD + d])
                            + x[(size_t)s * DD + d];
                    agg += gelu_exact(v);
                }
                s_in[r * DD + d] = fmaf(eps1, x[(size_t)n * DD + d], agg);
            }
        }
        __syncthreads();

        // ---- MLP layer 1 ----
        float a0 = bb1, a1 = bb1, a2 = bb1, a3 = bb1;
#pragma unroll
        for (int k4 = 0; k4 < 16; k4++) {
            float4 v0 = s_in4[0][k4], v1 = s_in4[1][k4], v2 = s_in4[2][k4], v3 = s_in4[3][k4];
            a0 = fmaf(v0.x, w1[4*k4+0], a0); a0 = fmaf(v0.y, w1[4*k4+1], a0);
            a0 = fmaf(v0.z, w1[4*k4+2], a0); a0 = fmaf(v0.w, w1[4*k4+3], a0);
            a1 = fmaf(v1.x, w1[4*k4+0], a1); a1 = fmaf(v1.y, w1[4*k4+1], a1);
            a1 = fmaf(v1.z, w1[4*k4+2], a1); a1 = fmaf(v1.w, w1[4*k4+3], a1);
            a2 = fmaf(v2.x, w1[4*k4+0], a2); a2 = fmaf(v2.y, w1[4*k4+1], a2);
            a2 = fmaf(v2.z, w1[4*k4+2], a2); a2 = fmaf(v2.w, w1[4*k4+3], a2);
            a3 = fmaf(v3.x, w1[4*k4+0], a3); a3 = fmaf(v3.y, w1[4*k4+1], a3);
            a3 = fmaf(v3.z, w1[4*k4+2], a3); a3 = fmaf(v3.w, w1[4*k4+3], a3);
        }
        s_h1[0 * DD + d] = gelu_exact(a0);
        s_h1[1 * DD + d] = gelu_exact(a1);
        s_h1[2 * DD + d] = gelu_exact(a2);
        s_h1[3 * DD + d] = gelu_exact(a3);
        __syncthreads();

        // ---- MLP layer 2 ----
        float c0 = bb2, c1 = bb2, c2 = bb2, c3 = bb2;
#pragma unroll
        for (int k4 = 0; k4 < 16; k4++) {
            float4 v0 = s_h14[0][k4], v1 = s_h14[1][k4], v2 = s_h14[2][k4], v3 = s_h14[3][k4];
            c0 = fmaf(v0.x, w2[4*k4+0], c0); c0 = fmaf(v0.y, w2[4*k4+1], c0);
            c0 = fmaf(v0.z, w2[4*k4+2], c0); c0 = fmaf(v0.w, w2[4*k4+3], c0);
            c1 = fmaf(v1.x, w2[4*k4+0], c1); c1 = fmaf(v1.y, w2[4*k4+1], c1);
            c1 = fmaf(v1.z, w2[4*k4+2], c1); c1 = fmaf(v1.w, w2[4*k4+3], c1);
            c2 = fmaf(v2.x, w2[4*k4+0], c2); c2 = fmaf(v2.y, w2[4*k4+1], c2);
            c2 = fmaf(v2.z, w2[4*k4+2], c2); c2 = fmaf(v2.w, w2[4*k4+3], c2);
            c3 = fmaf(v3.x, w2[4*k4+0], c3); c3 = fmaf(v3.y, w2[4*k4+1], c3);
            c3 = fmaf(v3.z, w2[4*k4+2], c3); c3 = fmaf(v3.w, w2[4*k4+3], c3);
        }
        float cc[4] = {c0, c1, c2, c3};
#pragma unroll
        for (int r = 0; r < 4; r++) {
            if (r < nr) {
                g_h[(size_t)(base + r) * DD + d] = cc[r];
                lsum += cc[r];
                lsq = fmaf(cc[r], cc[r], lsq);
            }
        }
        __syncthreads();
    }
    atomicAdd(&g_bsum[d], lsum);
    atomicAdd(&g_bsq[d],  lsq);
}

// ============================================================
// K_bn: x_next = (x + gelu(BN(h))) * INV_SQRT2
// ============================================================
__global__ void k_bn(int xsel, const float* __restrict__ xext,
                     int osel, float* __restrict__ oext,
                     const float* __restrict__ gamma,
                     const float* __restrict__ beta, int N)
{
    int idx = blockIdx.x * blockDim.x + threadIdx.x;
    int tot = N * 16;
    if (idx >= tot) return;
    const float* xin = sel_in(xsel, xext);
    float* xout = sel_out(osel, oext);

    int q = idx & 15;
    float invN = 1.0f / (float)N;
    float4 hv = ((const float4*)g_h)[idx];
    float4 xv = ((const float4*)xin)[idx];
    float hvv[4] = {hv.x, hv.y, hv.z, hv.w};
    float xvv[4] = {xv.x, xv.y, xv.z, xv.w};
    float o[4];
#pragma unroll
    for (int j = 0; j < 4; j++) {
        int dd = q * 4 + j;
        float mu   = g_bsum[dd] * invN;
        float var  = g_bsq[dd] * invN - mu * mu;
        float rstd = rsqrtf(var + 1e-5f);
        float hn   = (hvv[j] - mu) * rstd * gamma[dd] + beta[dd];
        o[j] = (xvv[j] + gelu_exact(hn)) * INV_SQRT2;
    }
    ((float4*)xout)[idx] = make_float4(o[0], o[1], o[2], o[3]);
}

// ============================================================
// launcher
// ============================================================
extern "C" void kernel_launch(void* const* d_in, const int* in_sizes, int n_in,
                              void* d_out, int out_size)
{
    const float* x0    = (const float*)d_in[0];
    const int*   eidx  = (const int*)  d_in[1];
    const float* eattr = (const float*)d_in[2];
    const float* Wbe   = (const float*)d_in[3];
    const float* bbe   = (const float*)d_in[4];
    const float* epsp  = (const float*)d_in[5];
    const float* W1    = (const float*)d_in[6];
    const float* b1    = (const float*)d_in[7];
    const float* W2    = (const float*)d_in[8];
    const float* b2    = (const float*)d_in[9];
    const float* gamma = (const float*)d_in[10];
    const float* beta  = (const float*)d_in[11];

    int N = in_sizes[0] / DD;
    int E = in_sizes[1] / 2;
    const int* src = eidx;
    const int* dst = eidx + E;

    // ---- one-time sort of edges by dst ----
    k_cnt0   <<<(N + 255) / 256, 256>>>(N);
    k_count  <<<(E + 255) / 256, 256>>>(dst, E);
    k_scan   <<<1, 1024>>>(N, E);
    k_scatter<<<(E + 255) / 256, 256>>>(src, dst, E);

    // ---- bond encoder once, fp16 output in sorted order ----
    k_bond<<<4736, 64>>>(eattr, Wbe, bbe, E);

    // x schedule: L0: ext(x0)->g_xa ; L1: g_xa->g_xb ; L2: g_xb->ext(d_out)
    int in_sel[3]  = {0, 1, 2};
    int out_sel[3] = {1, 2, 0};

    int nblk_node = (N * 16 + 255) / 256;

    for (int l = 0; l < 3; l++) {
        const float* xext = (l == 0) ? x0 : nullptr;
        k_zstat<<<1, 64>>>();
        k_mlp<<<2048, 64>>>(in_sel[l], xext,
                            W1 + (size_t)l * DD * DD, b1 + (size_t)l * DD,
                            W2 + (size_t)l * DD * DD, b2 + (size_t)l * DD,
                            epsp, l, N);
        k_bn <<<nblk_node, 256>>>(in_sel[l], xext, out_sel[l], (float*)d_out,
                                  gamma + (size_t)l * DD, beta + (size_t)l * DD, N);
    }
}

// round 5
// speedup vs baseline: 2.5851x; 2.5851x over previous
#include <cuda_runtime.h>
#include <cuda_fp16.h>
#include <math.h>

#define DD 64
#define NMAX 50000
#define EMAX 800000
#define INV_SQRT2 0.70710678118654752440f

// ---- scratch (device globals: allocation-free) ----
__device__ __half g_embh[(size_t)EMAX * DD]; // bond output fp16, natural edge order (102MB)
__device__ float g_agg[(size_t)NMAX * DD];   // scatter-add target
__device__ float g_h[(size_t)NMAX * DD];     // MLP output (pre-BN)
__device__ float g_xa[(size_t)NMAX * DD];    // x ping
__device__ float g_xb[(size_t)NMAX * DD];    // x pong
__device__ float g_bsum[DD];                 // BN sum per feature
__device__ float g_bsq[DD];                  // BN sumsq per feature

__device__ __forceinline__ float gelu_exact(float v) {
    // jax.nn.gelu(approximate=False) = 0.5 v (1 + erf(v/sqrt2))
    return 0.5f * v * (1.0f + erff(v * 0.70710678118654752440f));
}

__device__ __forceinline__ const float* sel_in(int s, const float* ext) {
    return (s == 0) ? ext : ((s == 1) ? g_xa : g_xb);
}
__device__ __forceinline__ float* sel_out(int s, float* ext) {
    return (s == 0) ? ext : ((s == 1) ? g_xa : g_xb);
}

// ============================================================
// K_bond: emb = attr @ W_be + b_be -> fp16, natural order.
// 256 threads = (row r=0..3, dim d=0..63): each thread one
// independent 64-FMA chain; attr float4 loads are warp-uniform
// broadcasts. Grid-stride over row groups of 4.
// ============================================================
__global__ void __launch_bounds__(256) k_bond(
    const float* __restrict__ attr,
    const float* __restrict__ Wbe,
    const float* __restrict__ bbe, int E)
{
    int r = threadIdx.x >> 6;      // 0..3 (warp-pair shares r)
    int d = threadIdx.x & 63;

    float w[DD];
#pragma unroll
    for (int k = 0; k < DD; k++) w[k] = Wbe[k * DD + d];
    float bias = bbe[d];

    for (int base = blockIdx.x * 4; base < E; base += gridDim.x * 4) {
        int row = base + r;
        if (row >= E) continue;
        const float4* a4 = (const float4*)(attr + (size_t)row * DD);
        float acc = bias;
#pragma unroll
        for (int k4 = 0; k4 < 16; k4++) {
            float4 a = a4[k4];
            acc = fmaf(a.x, w[4 * k4 + 0], acc);
            acc = fmaf(a.y, w[4 * k4 + 1], acc);
            acc = fmaf(a.z, w[4 * k4 + 2], acc);
            acc = fmaf(a.w, w[4 * k4 + 3], acc);
        }
        g_embh[(size_t)row * DD + d] = __float2half_rn(acc);
    }
}

// ============================================================
// K_zero: zero agg + BN stats
// ============================================================
__global__ void k_zero(int N)
{
    int idx = blockIdx.x * blockDim.x + threadIdx.x;
    if (idx < N * 16) ((float4*)g_agg)[idx] = make_float4(0.f, 0.f, 0.f, 0.f);
    if (blockIdx.x == 0 && threadIdx.x < DD) {
        g_bsum[threadIdx.x] = 0.f;
        g_bsq[threadIdx.x]  = 0.f;
    }
}

// ============================================================
// K_msg: m = gelu(x[src] + emb); agg[dst] += m  (16B vector RED)
// one thread per (edge, 4-dim group); emb read as fp16x4.
// ============================================================
__global__ void k_msg(int xsel, const float* __restrict__ xext,
                      const int* __restrict__ src,
                      const int* __restrict__ dst, int E)
{
    int idx = blockIdx.x * blockDim.x + threadIdx.x;
    if (idx >= E * 16) return;
    const float* x = sel_in(xsel, xext);
    int e = idx >> 4, q = idx & 15;
    int s = src[e], t = dst[e];

    uint2 raw = ((const uint2*)g_embh)[(size_t)e * 16 + q];
    float2 e01 = __half22float2(*(__half2*)&raw.x);
    float2 e23 = __half22float2(*(__half2*)&raw.y);
    float4 xs  = ((const float4*)x)[(size_t)s * 16 + q];

    float4 v;
    v.x = gelu_exact(e01.x + xs.x);
    v.y = gelu_exact(e01.y + xs.y);
    v.z = gelu_exact(e23.x + xs.z);
    v.w = gelu_exact(e23.y + xs.w);

    float4* p = ((float4*)g_agg) + (size_t)t * 16 + q;
#if defined(__CUDA_ARCH__) && (__CUDA_ARCH__ >= 900)
    atomicAdd(p, v);
#else
    float* pf = (float*)p;
    atomicAdd(pf + 0, v.x);
    atomicAdd(pf + 1, v.y);
    atomicAdd(pf + 2, v.z);
    atomicAdd(pf + 3, v.w);
#endif
}

// ============================================================
// K_mlp: h = gelu(((1+eps)x + agg) @ W1 + b1) @ W2 + b2 ; BN stats.
// 64 threads/block (thread owns dim d), 4 rows/iter = 4 chains.
// ============================================================
__global__ void __launch_bounds__(64) k_mlp(
    int xsel, const float* __restrict__ xext,
    const float* __restrict__ W1, const float* __restrict__ b1,
    const float* __restrict__ W2, const float* __restrict__ b2,
    const float* __restrict__ epsp, int layer, int N)
{
    __shared__ float4 s_in4[4][16];
    __shared__ float4 s_h14[4][16];
    float* s_in = (float*)s_in4;
    float* s_h1 = (float*)s_h14;

    const float* x = sel_in(xsel, xext);
    int d = threadIdx.x;

    float w1[DD], w2[DD];
#pragma unroll
    for (int k = 0; k < DD; k++) w1[k] = W1[k * DD + d];
#pragma unroll
    for (int k = 0; k < DD; k++) w2[k] = W2[k * DD + d];
    float bb1 = b1[d], bb2 = b2[d];
    float eps1 = 1.0f + epsp[layer];

    float lsum = 0.f, lsq = 0.f;

    for (int base = blockIdx.x * 4; base < N; base += gridDim.x * 4) {
        int nr = min(4, N - base);
#pragma unroll
        for (int r = 0; r < 4; r++)
            if (r < nr)
                s_in[r * DD + d] = fmaf(eps1, x[(size_t)(base + r) * DD + d],
                                        g_agg[(size_t)(base + r) * DD + d]);
        __syncthreads();

        float a0 = bb1, a1 = bb1, a2 = bb1, a3 = bb1;
#pragma unroll
        for (int k4 = 0; k4 < 16; k4++) {
            float4 v0 = s_in4[0][k4], v1 = s_in4[1][k4], v2 = s_in4[2][k4], v3 = s_in4[3][k4];
            a0 = fmaf(v0.x, w1[4*k4+0], a0); a0 = fmaf(v0.y, w1[4*k4+1], a0);
            a0 = fmaf(v0.z, w1[4*k4+2], a0); a0 = fmaf(v0.w, w1[4*k4+3], a0);
            a1 = fmaf(v1.x, w1[4*k4+0], a1); a1 = fmaf(v1.y, w1[4*k4+1], a1);
            a1 = fmaf(v1.z, w1[4*k4+2], a1); a1 = fmaf(v1.w, w1[4*k4+3], a1);
            a2 = fmaf(v2.x, w1[4*k4+0], a2); a2 = fmaf(v2.y, w1[4*k4+1], a2);
            a2 = fmaf(v2.z, w1[4*k4+2], a2); a2 = fmaf(v2.w, w1[4*k4+3], a2);
            a3 = fmaf(v3.x, w1[4*k4+0], a3); a3 = fmaf(v3.y, w1[4*k4+1], a3);
            a3 = fmaf(v3.z, w1[4*k4+2], a3); a3 = fmaf(v3.w, w1[4*k4+3], a3);
        }
        s_h1[0 * DD + d] = gelu_exact(a0);
        s_h1[1 * DD + d] = gelu_exact(a1);
        s_h1[2 * DD + d] = gelu_exact(a2);
        s_h1[3 * DD + d] = gelu_exact(a3);
        __syncthreads();

        float c0 = bb2, c1 = bb2, c2 = bb2, c3 = bb2;
#pragma unroll
        for (int k4 = 0; k4 < 16; k4++) {
            float4 v0 = s_h14[0][k4], v1 = s_h14[1][k4], v2 = s_h14[2][k4], v3 = s_h14[3][k4];
            c0 = fmaf(v0.x, w2[4*k4+0], c0); c0 = fmaf(v0.y, w2[4*k4+1], c0);
            c0 = fmaf(v0.z, w2[4*k4+2], c0); c0 = fmaf(v0.w, w2[4*k4+3], c0);
            c1 = fmaf(v1.x, w2[4*k4+0], c1); c1 = fmaf(v1.y, w2[4*k4+1], c1);
            c1 = fmaf(v1.z, w2[4*k4+2], c1); c1 = fmaf(v1.w, w2[4*k4+3], c1);
            c2 = fmaf(v2.x, w2[4*k4+0], c2); c2 = fmaf(v2.y, w2[4*k4+1], c2);
            c2 = fmaf(v2.z, w2[4*k4+2], c2); c2 = fmaf(v2.w, w2[4*k4+3], c2);
            c3 = fmaf(v3.x, w2[4*k4+0], c3); c3 = fmaf(v3.y, w2[4*k4+1], c3);
            c3 = fmaf(v3.z, w2[4*k4+2], c3); c3 = fmaf(v3.w, w2[4*k4+3], c3);
        }
        float cc[4] = {c0, c1, c2, c3};
#pragma unroll
        for (int r = 0; r < 4; r++) {
            if (r < nr) {
                g_h[(size_t)(base + r) * DD + d] = cc[r];
                lsum += cc[r];
                lsq = fmaf(cc[r], cc[r], lsq);
            }
        }
        __syncthreads();
    }
    atomicAdd(&g_bsum[d], lsum);
    atomicAdd(&g_bsq[d],  lsq);
}

// ============================================================
// K_bn: x_next = (x + gelu(BN(h))) * INV_SQRT2
// ============================================================
__global__ void k_bn(int xsel, const float* __restrict__ xext,
                     int osel, float* __restrict__ oext,
                     const float* __restrict__ gamma,
                     const float* __restrict__ beta, int N)
{
    int idx = blockIdx.x * blockDim.x + threadIdx.x;
    if (idx >= N * 16) return;
    const float* xin = sel_in(xsel, xext);
    float* xout = sel_out(osel, oext);

    int q = idx & 15;
    float invN = 1.0f / (float)N;
    float4 hv = ((const float4*)g_h)[idx];
    float4 xv = ((const float4*)xin)[idx];
    float hvv[4] = {hv.x, hv.y, hv.z, hv.w};
    float xvv[4] = {xv.x, xv.y, xv.z, xv.w};
    float o[4];
#pragma unroll
    for (int j = 0; j < 4; j++) {
        int dd = q * 4 + j;
        float mu   = g_bsum[dd] * invN;
        float var  = g_bsq[dd] * invN - mu * mu;
        float rstd = rsqrtf(var + 1e-5f);
        float hn   = (hvv[j] - mu) * rstd * gamma[dd] + beta[dd];
        o[j] = (xvv[j] + gelu_exact(hn)) * INV_SQRT2;
    }
    ((float4*)xout)[idx] = make_float4(o[0], o[1], o[2], o[3]);
}

// ============================================================
// launcher
// ============================================================
extern "C" void kernel_launch(void* const* d_in, const int* in_sizes, int n_in,
                              void* d_out, int out_size)
{
    const float* x0    = (const float*)d_in[0];
    const int*   eidx  = (const int*)  d_in[1];
    const float* eattr = (const float*)d_in[2];
    const float* Wbe   = (const float*)d_in[3];
    const float* bbe   = (const float*)d_in[4];
    const float* epsp  = (const float*)d_in[5];
    const float* W1    = (const float*)d_in[6];
    const float* b1    = (const float*)d_in[7];
    const float* W2    = (const float*)d_in[8];
    const float* b2    = (const float*)d_in[9];
    const float* gamma = (const float*)d_in[10];
    const float* beta  = (const float*)d_in[11];

    int N = in_sizes[0] / DD;
    int E = in_sizes[1] / 2;
    const int* src = eidx;
    const int* dst = eidx + E;

    // bond encoder once (fp16, natural order)
    k_bond<<<4736, 256>>>(eattr, Wbe, bbe, E);

    // x schedule: L0: ext(x0)->g_xa ; L1: g_xa->g_xb ; L2: g_xb->ext(d_out)
    int in_sel[3]  = {0, 1, 2};
    int out_sel[3] = {1, 2, 0};

    int nblk_node = (N * 16 + 255) / 256;
    int nblk_edge = (E * 16 + 255) / 256;

    for (int l = 0; l < 3; l++) {
        const float* xext = (l == 0) ? x0 : nullptr;
        k_zero<<<nblk_node, 256>>>(N);
        k_msg <<<nblk_edge, 256>>>(in_sel[l], xext, src, dst, E);
        k_mlp <<<2048, 64>>>(in_sel[l], xext,
                             W1 + (size_t)l * DD * DD, b1 + (size_t)l * DD,
                             W2 + (size_t)l * DD * DD, b2 + (size_t)l * DD,
                             epsp, l, N);
        k_bn <<<nblk_node, 256>>>(in_sel[l], xext, out_sel[l], (float*)d_out,
                                  gamma + (size_t)l * DD, beta + (size_t)l * DD, N);
    }
}

// round 6
// speedup vs baseline: 2.7127x; 1.0493x over previous
#include <cuda_runtime.h>
#include <cuda_fp16.h>
#include <math.h>

#define DD 64
#define NMAX 50000
#define EMAX 800000
#define INV_SQRT2 0.70710678118654752440f

typedef unsigned long long u64;

// ---- scratch (device globals: allocation-free) ----
__device__ __half g_embh[(size_t)EMAX * DD]; // bond output fp16, natural edge order
__device__ float g_agg[(size_t)NMAX * DD];   // scatter-add target
__device__ float g_h[(size_t)NMAX * DD];     // MLP output (pre-BN)
__device__ float g_xa[(size_t)NMAX * DD];    // x ping
__device__ float g_xb[(size_t)NMAX * DD];    // x pong
__device__ float g_bsum[3][DD];              // BN sum per layer/feature
__device__ float g_bsq[3][DD];               // BN sumsq per layer/feature

// ---- packed f32x2 helpers ----
__device__ __forceinline__ u64 pack2(float lo, float hi) {
    u64 r; asm("mov.b64 %0, {%1, %2};" : "=l"(r) : "f"(lo), "f"(hi)); return r;
}
__device__ __forceinline__ void ffma2(u64& acc, u64 a, u64 b) {
    asm("fma.rn.f32x2 %0, %1, %2, %0;" : "+l"(acc) : "l"(a), "l"(b));
}
__device__ __forceinline__ float unpack_sum(u64 v) {
    float lo, hi; asm("mov.b64 {%0, %1}, %2;" : "=f"(lo), "=f"(hi) : "l"(v));
    return lo + hi;
}

__device__ __forceinline__ float gelu_exact(float v) {
    return 0.5f * v * (1.0f + erff(v * 0.70710678118654752440f));
}

__device__ __forceinline__ const float* sel_in(int s, const float* ext) {
    return (s == 0) ? ext : ((s == 1) ? g_xa : g_xb);
}
__device__ __forceinline__ float* sel_out(int s, float* ext) {
    return (s == 0) ? ext : ((s == 1) ? g_xa : g_xb);
}

// ============================================================
// K_bond: emb = attr @ W_be + b_be -> fp16, natural order.
// 256 thr = 4 rows x 64 dims. Packed f32x2 over adjacent k:
// attr row read as ulonglong2 (two f32x2 operands per 16B, no movs),
// weights pre-packed {W[k][d], W[k+1][d]} in 64 regs.
// ============================================================
__global__ void __launch_bounds__(256) k_bond(
    const float* __restrict__ attr,
    const float* __restrict__ Wbe,
    const float* __restrict__ bbe, int E)
{
    int r = threadIdx.x >> 6;
    int d = threadIdx.x & 63;

    u64 wp[32];
#pragma unroll
    for (int j = 0; j < 32; j++)
        wp[j] = pack2(Wbe[(2 * j) * DD + d], Wbe[(2 * j + 1) * DD + d]);
    float bias = bbe[d];

    for (int base = blockIdx.x * 4; base < E; base += gridDim.x * 4) {
        int row = base + r;
        if (row >= E) continue;
        const ulonglong2* a2 = (const ulonglong2*)(attr + (size_t)row * DD);
        u64 acc = 0;  // {0.f, 0.f}
#pragma unroll
        for (int k4 = 0; k4 < 16; k4++) {
            ulonglong2 a = a2[k4];
            ffma2(acc, a.x, wp[2 * k4]);
            ffma2(acc, a.y, wp[2 * k4 + 1]);
        }
        g_embh[(size_t)row * DD + d] = __float2half_rn(unpack_sum(acc) + bias);
    }
}

// ============================================================
// K_zero: zero agg (layer 0) + all BN stat slots, once per launch
// ============================================================
__global__ void k_zero(int N)
{
    int idx = blockIdx.x * blockDim.x + threadIdx.x;
    if (idx < N * 16) ((float4*)g_agg)[idx] = make_float4(0.f, 0.f, 0.f, 0.f);
    if (blockIdx.x == 0 && threadIdx.x < 3 * DD) {
        ((float*)g_bsum)[threadIdx.x] = 0.f;
        ((float*)g_bsq)[threadIdx.x]  = 0.f;
    }
}

// ============================================================
// K_msg: m = gelu(x[src] + emb); agg[dst] += m
// one thread per (edge, 8-dim group): 1 LDG.128 emb, 2 float4 x,
// 8 gelu, 2 vector atomics.
// ============================================================
__global__ void k_msg(int xsel, const float* __restrict__ xext,
                      const int* __restrict__ src,
                      const int* __restrict__ dst, int E)
{
    int idx = blockIdx.x * blockDim.x + threadIdx.x;
    if (idx >= E * 8) return;
    const float* x = sel_in(xsel, xext);
    int e = idx >> 3, q = idx & 7;
    int s = src[e], t = dst[e];

    uint4 eh = ((const uint4*)g_embh)[(size_t)e * 8 + q];
    float2 e0 = __half22float2(*(__half2*)&eh.x);
    float2 e1 = __half22float2(*(__half2*)&eh.y);
    float2 e2 = __half22float2(*(__half2*)&eh.z);
    float2 e3 = __half22float2(*(__half2*)&eh.w);

    float4 x0 = ((const float4*)x)[(size_t)s * 16 + q * 2];
    float4 x1 = ((const float4*)x)[(size_t)s * 16 + q * 2 + 1];

    float4 m0, m1;
    m0.x = gelu_exact(e0.x + x0.x);
    m0.y = gelu_exact(e0.y + x0.y);
    m0.z = gelu_exact(e1.x + x0.z);
    m0.w = gelu_exact(e1.y + x0.w);
    m1.x = gelu_exact(e2.x + x1.x);
    m1.y = gelu_exact(e2.y + x1.y);
    m1.z = gelu_exact(e3.x + x1.z);
    m1.w = gelu_exact(e3.y + x1.w);

    float4* p = ((float4*)g_agg) + (size_t)t * 16 + q * 2;
#if defined(__CUDA_ARCH__) && (__CUDA_ARCH__ >= 900)
    atomicAdd(p,     m0);
    atomicAdd(p + 1, m1);
#else
    float* pf = (float*)p;
    atomicAdd(pf + 0, m0.x); atomicAdd(pf + 1, m0.y);
    atomicAdd(pf + 2, m0.z); atomicAdd(pf + 3, m0.w);
    atomicAdd(pf + 4, m1.x); atomicAdd(pf + 5, m1.y);
    atomicAdd(pf + 6, m1.z); atomicAdd(pf + 7, m1.w);
#endif
}

// ============================================================
// K_mlp: h = gelu(((1+eps)x + agg) @ W1 + b1) @ W2 + b2 ; BN stats.
// 64 threads (thread owns dim d), 4 rows/iter, packed f32x2 inner loops.
// ============================================================
__global__ void __launch_bounds__(64) k_mlp(
    int xsel, const float* __restrict__ xext,
    const float* __restrict__ W1, const float* __restrict__ b1,
    const float* __restrict__ W2, const float* __restrict__ b2,
    const float* __restrict__ epsp, int layer, int N)
{
    __shared__ __align__(16) float s_in[4][DD];
    __shared__ __align__(16) float s_h1[4][DD];

    const float* x = sel_in(xsel, xext);
    int d = threadIdx.x;

    u64 w1p[32], w2p[32];
#pragma unroll
    for (int j = 0; j < 32; j++) {
        w1p[j] = pack2(W1[(2 * j) * DD + d], W1[(2 * j + 1) * DD + d]);
        w2p[j] = pack2(W2[(2 * j) * DD + d], W2[(2 * j + 1) * DD + d]);
    }
    float bb1 = b1[d], bb2 = b2[d];
    float eps1 = 1.0f + epsp[layer];

    float lsum = 0.f, lsq = 0.f;

    for (int base = blockIdx.x * 4; base < N; base += gridDim.x * 4) {
        int nr = min(4, N - base);
#pragma unroll
        for (int r = 0; r < 4; r++)
            if (r < nr)
                s_in[r][d] = fmaf(eps1, x[(size_t)(base + r) * DD + d],
                                  g_agg[(size_t)(base + r) * DD + d]);
        __syncthreads();

        {
            const ulonglong2* r0 = (const ulonglong2*)s_in[0];
            const ulonglong2* r1 = (const ulonglong2*)s_in[1];
            const ulonglong2* r2 = (const ulonglong2*)s_in[2];
            const ulonglong2* r3 = (const ulonglong2*)s_in[3];
            u64 A0 = 0, A1 = 0, A2 = 0, A3 = 0;
#pragma unroll
            for (int k4 = 0; k4 < 16; k4++) {
                ulonglong2 v0 = r0[k4], v1 = r1[k4], v2 = r2[k4], v3 = r3[k4];
                ffma2(A0, v0.x, w1p[2*k4]); ffma2(A0, v0.y, w1p[2*k4+1]);
                ffma2(A1, v1.x, w1p[2*k4]); ffma2(A1, v1.y, w1p[2*k4+1]);
                ffma2(A2, v2.x, w1p[2*k4]); ffma2(A2, v2.y, w1p[2*k4+1]);
                ffma2(A3, v3.x, w1p[2*k4]); ffma2(A3, v3.y, w1p[2*k4+1]);
            }
            s_h1[0][d] = gelu_exact(unpack_sum(A0) + bb1);
            s_h1[1][d] = gelu_exact(unpack_sum(A1) + bb1);
            s_h1[2][d] = gelu_exact(unpack_sum(A2) + bb1);
            s_h1[3][d] = gelu_exact(unpack_sum(A3) + bb1);
        }
        __syncthreads();

        {
            const ulonglong2* r0 = (const ulonglong2*)s_h1[0];
            const ulonglong2* r1 = (const ulonglong2*)s_h1[1];
            const ulonglong2* r2 = (const ulonglong2*)s_h1[2];
            const ulonglong2* r3 = (const ulonglong2*)s_h1[3];
            u64 C0 = 0, C1 = 0, C2 = 0, C3 = 0;
#pragma unroll
            for (int k4 = 0; k4 < 16; k4++) {
                ulonglong2 v0 = r0[k4], v1 = r1[k4], v2 = r2[k4], v3 = r3[k4];
                ffma2(C0, v0.x, w2p[2*k4]); ffma2(C0, v0.y, w2p[2*k4+1]);
                ffma2(C1, v1.x, w2p[2*k4]); ffma2(C1, v1.y, w2p[2*k4+1]);
                ffma2(C2, v2.x, w2p[2*k4]); ffma2(C2, v2.y, w2p[2*k4+1]);
                ffma2(C3, v3.x, w2p[2*k4]); ffma2(C3, v3.y, w2p[2*k4+1]);
            }
            float cc[4];
            cc[0] = unpack_sum(C0) + bb2;
            cc[1] = unpack_sum(C1) + bb2;
            cc[2] = unpack_sum(C2) + bb2;
            cc[3] = unpack_sum(C3) + bb2;
#pragma unroll
            for (int r = 0; r < 4; r++) {
                if (r < nr) {
                    g_h[(size_t)(base + r) * DD + d] = cc[r];
                    lsum += cc[r];
                    lsq = fmaf(cc[r], cc[r], lsq);
                }
            }
        }
        __syncthreads();
    }
    atomicAdd(&g_bsum[layer][d], lsum);
    atomicAdd(&g_bsq[layer][d],  lsq);
}

// ============================================================
// K_bn: x_next = (x + gelu(BN(h))) * INV_SQRT2 ; zero agg for next layer
// ============================================================
__global__ void k_bn(int xsel, const float* __restrict__ xext,
                     int osel, float* __restrict__ oext,
                     const float* __restrict__ gamma,
                     const float* __restrict__ beta, int layer, int N)
{
    int idx = blockIdx.x * blockDim.x + threadIdx.x;
    if (idx >= N * 16) return;
    const float* xin = sel_in(xsel, xext);
    float* xout = sel_out(osel, oext);

    int q = idx & 15;
    float invN = 1.0f / (float)N;
    float4 hv = ((const float4*)g_h)[idx];
    float4 xv = ((const float4*)xin)[idx];
    float hvv[4] = {hv.x, hv.y, hv.z, hv.w};
    float xvv[4] = {xv.x, xv.y, xv.z, xv.w};
    float o[4];
#pragma unroll
    for (int j = 0; j < 4; j++) {
        int dd = q * 4 + j;
        float mu   = g_bsum[layer][dd] * invN;
        float var  = g_bsq[layer][dd] * invN - mu * mu;
        float rstd = rsqrtf(var + 1e-5f);
        float hn   = (hvv[j] - mu) * rstd * gamma[dd] + beta[dd];
        o[j] = (xvv[j] + gelu_exact(hn)) * INV_SQRT2;
    }
    ((float4*)xout)[idx] = make_float4(o[0], o[1], o[2], o[3]);
    // zero agg for the next layer's scatter (free: same index space)
    ((float4*)g_agg)[idx] = make_float4(0.f, 0.f, 0.f, 0.f);
}

// ============================================================
// launcher
// ============================================================
extern "C" void kernel_launch(void* const* d_in, const int* in_sizes, int n_in,
                              void* d_out, int out_size)
{
    const float* x0    = (const float*)d_in[0];
    const int*   eidx  = (const int*)  d_in[1];
    const float* eattr = (const float*)d_in[2];
    const float* Wbe   = (const float*)d_in[3];
    const float* bbe   = (const float*)d_in[4];
    const float* epsp  = (const float*)d_in[5];
    const float* W1    = (const float*)d_in[6];
    const float* b1    = (const float*)d_in[7];
    const float* W2    = (const float*)d_in[8];
    const float* b2    = (const float*)d_in[9];
    const float* gamma = (const float*)d_in[10];
    const float* beta  = (const float*)d_in[11];

    int N = in_sizes[0] / DD;
    int E = in_sizes[1] / 2;
    const int* src = eidx;
    const int* dst = eidx + E;

    // zero agg + BN stats (independent of bond)
    k_zero<<<(N * 16 + 255) / 256, 256>>>(N);
    // bond encoder once (fp16, natural order)
    k_bond<<<4736, 256>>>(eattr, Wbe, bbe, E);

    // x schedule: L0: ext(x0)->g_xa ; L1: g_xa->g_xb ; L2: g_xb->ext(d_out)
    int in_sel[3]  = {0, 1, 2};
    int out_sel[3] = {1, 2, 0};

    int nblk_node = (N * 16 + 255) / 256;
    int nblk_edge = (E * 8 + 255) / 256;

    for (int l = 0; l < 3; l++) {
        const float* xext = (l == 0) ? x0 : nullptr;
        k_msg<<<nblk_edge, 256>>>(in_sel[l], xext, src, dst, E);
        k_mlp<<<2048, 64>>>(in_sel[l], xext,
                            W1 + (size_t)l * DD * DD, b1 + (size_t)l * DD,
                            W2 + (size_t)l * DD * DD, b2 + (size_t)l * DD,
                            epsp, l, N);
        k_bn<<<nblk_node, 256>>>(in_sel[l], xext, out_sel[l], (float*)d_out,
                                 gamma + (size_t)l * DD, beta + (size_t)l * DD, l, N);
    }
}